// round 10
// baseline (speedup 1.0000x reference)
#include <cuda_runtime.h>
#include <cuda_bf16.h>
#include <cuda_fp16.h>
#include <cstdint>

#define NB 4
#define NPIX 4096
#define CDIM 256
#define CK 32
#define TOTPIX (NB*NPIX)
#define LOG2E 1.4426950408889634f
#define SHIFT 28.853900817779268f   // 20 * log2(e)

__device__ __half g_k[TOTPIX*CK];                   // keys fp16
__device__ __half g_q[TOTPIX*CK];                   // queries fp16, pre-scaled log2e
__device__ __nv_bfloat16 g_hT[(size_t)CDIM*TOTPIX]; // values bf16, channel-major
__device__ __nv_bfloat16 g_xs[(size_t)TOTPIX*512];  // [px][ xh(256) | xl(256) ]
__device__ __nv_bfloat16 g_wT[320*768];             // [col][ Whi | Whi | Wlo ]

__device__ __forceinline__ uint32_t bf2u32(float a, float b) {
    __nv_bfloat162 h = __floats2bfloat162_rn(a, b);
    return *reinterpret_cast<uint32_t*>(&h);
}
__device__ __forceinline__ void split_bf16(float v, __nv_bfloat16& hi, __nv_bfloat16& lo) {
    hi = __float2bfloat16_rn(v);
    lo = __float2bfloat16_rn(v - __bfloat162float(hi));
}
__device__ __forceinline__ uint32_t smem_u32(const void* p) {
    uint32_t r;
    asm("{ .reg .u64 t; cvta.to.shared.u64 t, %1; cvt.u32.u64 %0, t; }" : "=r"(r) : "l"(p));
    return r;
}
__device__ __forceinline__ float ex2(float x) {
    float y; asm("ex2.approx.f32 %0,%1;" : "=f"(y) : "f"(x)); return y;
}
__device__ __forceinline__ void mma_bf16(float* c, const uint32_t* a, uint32_t b0, uint32_t b1) {
    asm volatile(
        "mma.sync.aligned.m16n8k16.row.col.f32.bf16.bf16.f32 "
        "{%0,%1,%2,%3},{%4,%5,%6,%7},{%8,%9},{%0,%1,%2,%3};"
        : "+f"(c[0]), "+f"(c[1]), "+f"(c[2]), "+f"(c[3])
        : "r"(a[0]), "r"(a[1]), "r"(a[2]), "r"(a[3]), "r"(b0), "r"(b1));
}
__device__ __forceinline__ void mma_f16(float* c, const uint32_t* a, uint32_t b0, uint32_t b1) {
    asm volatile(
        "mma.sync.aligned.m16n8k16.row.col.f32.f16.f16.f32 "
        "{%0,%1,%2,%3},{%4,%5,%6,%7},{%8,%9},{%0,%1,%2,%3};"
        : "+f"(c[0]), "+f"(c[1]), "+f"(c[2]), "+f"(c[3])
        : "r"(a[0]), "r"(a[1]), "r"(a[2]), "r"(a[3]), "r"(b0), "r"(b1));
}
__device__ __forceinline__ void ldsm4(uint32_t addr, uint32_t* r) {
    asm volatile("ldmatrix.sync.aligned.m8n8.x4.shared.b16 {%0,%1,%2,%3},[%4];"
        : "=r"(r[0]), "=r"(r[1]), "=r"(r[2]), "=r"(r[3]) : "r"(addr));
}
__device__ __forceinline__ void stsm4(uint32_t addr, uint32_t r0, uint32_t r1,
                                      uint32_t r2, uint32_t r3) {
    asm volatile("stmatrix.sync.aligned.m8n8.x4.shared.b16 [%0], {%1,%2,%3,%4};"
        :: "r"(addr), "r"(r0), "r"(r1), "r"(r2), "r"(r3) : "memory");
}
__device__ __forceinline__ void cpa16(uint32_t dst, const void* src) {
    asm volatile("cp.async.cg.shared.global [%0],[%1],16;" :: "r"(dst), "l"(src) : "memory");
}
#define CPA_COMMIT() asm volatile("cp.async.commit_group;" ::: "memory")
#define CPA_WAIT(n)  asm volatile("cp.async.wait_group %0;" :: "n"(n) : "memory")

// swizzled layouts (stride = row bytes; swizzle bits [4:6] by row&7)
__device__ __forceinline__ uint32_t addrA(uint32_t base, int rbase, int kb, int stride, int lane) {
    int g = lane >> 3, lr = lane & 7;
    int r = rbase + lr + (g & 1) * 8;
    int kk = kb + (g & 2) * 8;
    return base + r * stride + (kk ^ ((r & 7) << 4));
}
__device__ __forceinline__ uint32_t addrB(uint32_t base, int rbase, int kb, int stride, int lane) {
    int g = lane >> 3, lr = lane & 7;
    int r = rbase + lr + (g & 2) * 4;
    int kk = kb + (g & 1) * 16;
    return base + r * stride + (kk ^ ((r & 7) << 4));
}
// packed 64B-rows (2 rows per 128B frame) layouts (Q, K) -- conflict-free
__device__ __forceinline__ uint32_t addrA_pk(uint32_t base, int rbase, int kb, int lane) {
    int g = lane >> 3, lr = lane & 7;
    int r = rbase + lr + (g & 1) * 8;
    int kk = kb + (g & 2) * 8;
    return base + (r >> 1)*128 + (r & 1)*64 + kk;
}
__device__ __forceinline__ uint32_t addrB_pk(uint32_t base, int rbase, int kb, int lane) {
    int g = lane >> 3, lr = lane & 7;
    int r = rbase + lr + (g & 2) * 4;
    int kk = kb + (g & 1) * 16;
    return base + (r >> 1)*128 + (r & 1)*64 + kk;
}

// ============================================================================
// Pre-kernel A: weight transpose/split -> g_wT[col][768]
// ============================================================================
__global__ __launch_bounds__(256) void wsplit_kernel(
    const float* __restrict__ Wf, const float* __restrict__ Wg,
    const float* __restrict__ Wh)
{
    const int col = blockIdx.x;
    const int k = threadIdx.x;
    float w;
    if (col < 256)      w = Wh[k*256 + col];
    else if (col < 288) w = Wf[k*32 + (col-256)];
    else                w = Wg[k*32 + (col-288)] * LOG2E;
    __nv_bfloat16 hi, lo;
    split_bf16(w, hi, lo);
    g_wT[col*768 + k]       = hi;
    g_wT[col*768 + 256 + k] = hi;
    g_wT[col*768 + 512 + k] = lo;
}

// ============================================================================
// Pre-kernel B: x hi/lo split -> g_xs[px][xh|xl]
// ============================================================================
__global__ __launch_bounds__(256) void xsplit_kernel(const float* __restrict__ x)
{
    const int gid = blockIdx.x * 256 + threadIdx.x;
    const int px = gid >> 5;
    const int seg = (gid & 31) * 8;
    float4 v0 = *(const float4*)(x + (size_t)px*256 + seg);
    float4 v1 = *(const float4*)(x + (size_t)px*256 + seg + 4);
    float vv[8] = {v0.x,v0.y,v0.z,v0.w,v1.x,v1.y,v1.z,v1.w};
    uint32_t H[4], L[4];
    #pragma unroll
    for (int i = 0; i < 4; i++) {
        __nv_bfloat16 h0,l0,h1,l1;
        split_bf16(vv[2*i],   h0, l0);
        split_bf16(vv[2*i+1], h1, l1);
        H[i] = (*(uint16_t*)&h0) | ((uint32_t)(*(uint16_t*)&h1) << 16);
        L[i] = (*(uint16_t*)&l0) | ((uint32_t)(*(uint16_t*)&l1) << 16);
    }
    *(uint4*)(g_xs + (size_t)px*512 + seg)       = make_uint4(H[0],H[1],H[2],H[3]);
    *(uint4*)(g_xs + (size_t)px*512 + 256 + seg) = make_uint4(L[0],L[1],L[2],L[3]);
}

// ============================================================================
// Projection GEMM: C[16384,320] = [xh|xl|xh] @ g_wT^T, K=768, 6 chunks.
// ============================================================================
#define PJ_AB   32768u
#define PJ_BB   16384u
#define PJ_SMEM (2*PJ_AB + 2*PJ_BB)

__device__ __forceinline__ void pj_copy(uint32_t smb, int t, int rows0, int c0, int n)
{
    static const int kxb[6] = {0,128,256,384,0,128};
    const uint32_t ab = smb + (uint32_t)(n & 1)*PJ_AB;
    const uint32_t bb = smb + 2*PJ_AB + (uint32_t)(n & 1)*PJ_BB;
    {
        const int r = t >> 1, half = t & 1;
        const __nv_bfloat16* src = g_xs + (size_t)(rows0 + r)*512 + kxb[n];
        #pragma unroll
        for (int i = 0; i < 8; i++) {
            int p = half*8 + i;
            cpa16(ab + r*256 + ((p*16) ^ ((r & 7) << 4)), src + p*8);
        }
    }
    {
        const int c = t >> 2, q = t & 3;
        const __nv_bfloat16* src = g_wT + (size_t)(c0 + c)*768 + n*128;
        #pragma unroll
        for (int i = 0; i < 4; i++) {
            int p = q*4 + i;
            cpa16(bb + c*256 + ((p*16) ^ ((c & 7) << 4)), src + p*8);
        }
    }
}

__global__ __launch_bounds__(256, 2) void proj_kernel(
    const float* __restrict__ bfp, const float* __restrict__ bgp,
    const float* __restrict__ bhp)
{
    extern __shared__ char sm[];
    const uint32_t smb = smem_u32(sm);
    const int t = threadIdx.x;
    const int w = t >> 5;
    const int lane = t & 31;
    const int rows0 = blockIdx.x * 128;
    const int c0 = blockIdx.y * 64;
    const int rs = (w & 3) * 32;
    const int cs = (w >> 2) * 32;

    float acc[2][4][4];
    #pragma unroll
    for (int m = 0; m < 2; m++)
        #pragma unroll
        for (int n = 0; n < 4; n++)
            { acc[m][n][0]=0.f; acc[m][n][1]=0.f; acc[m][n][2]=0.f; acc[m][n][3]=0.f; }

    pj_copy(smb, t, rows0, c0, 0);
    CPA_COMMIT();

    for (int n = 0; n < 6; n++) {
        if (n + 1 < 6) {
            pj_copy(smb, t, rows0, c0, n+1);
            CPA_COMMIT();
            CPA_WAIT(1);
        } else {
            CPA_WAIT(0);
        }
        __syncthreads();
        const uint32_t ab = smb + (uint32_t)(n & 1)*PJ_AB;
        const uint32_t bb = smb + 2*PJ_AB + (uint32_t)(n & 1)*PJ_BB;
        #pragma unroll
        for (int k16 = 0; k16 < 8; k16++) {
            uint32_t a0[4], a1[4];
            ldsm4(addrA(ab, rs,      k16*32, 256, lane), a0);
            ldsm4(addrA(ab, rs + 16, k16*32, 256, lane), a1);
            #pragma unroll
            for (int n16 = 0; n16 < 2; n16++) {
                uint32_t B[4];
                ldsm4(addrB(bb, cs + n16*16, k16*32, 256, lane), B);
                mma_bf16(acc[0][n16*2],   a0, B[0], B[1]);
                mma_bf16(acc[0][n16*2+1], a0, B[2], B[3]);
                mma_bf16(acc[1][n16*2],   a1, B[0], B[1]);
                mma_bf16(acc[1][n16*2+1], a1, B[2], B[3]);
            }
        }
        __syncthreads();
    }

    #pragma unroll
    for (int n = 0; n < 4; n++) {
        const int cA = cs + n*8 + (lane & 3)*2;
        #pragma unroll
        for (int half = 0; half < 2; half++) {
            const int gc = c0 + cA + half;
            float bias;
            if (gc < 256)      bias = bhp[gc];
            else if (gc < 288) bias = bfp[gc-256];
            else               bias = bgp[gc-288] * LOG2E;
            #pragma unroll
            for (int m = 0; m < 2; m++) {
                #pragma unroll
                for (int eh = 0; eh < 2; eh++) {
                    const int r = rs + m*16 + (lane >> 2) + eh*8;
                    const int px = rows0 + r;
                    float v = acc[m][n][eh*2 + half] + bias;
                    if (gc < 256) {
                        g_hT[(size_t)gc*TOTPIX + px] = __float2bfloat16_rn(v);
                    } else if (gc < 288) {
                        g_k[(size_t)px*CK + (gc-256)] = __float2half_rn(v);
                    } else {
                        g_q[(size_t)px*CK + (gc-288)] = __float2half_rn(v);
                    }
                }
            }
        }
    }
}

// ============================================================================
// Flash attention: 64 q/block, 8 warps, 2 CTAs/SM, software-pipelined.
// j-tile 64, K/V double-buffered (K prefetch dist 2, V dist 1), P double.
//   warp (rg = w&1: 32 q-rows) x (cg = w>>1: 16 S-cols / 64-d quarter)
// ============================================================================
#define JT 64
#define NIT (NPIX/JT)
#define OFF_LS 0u
#define OFF_Q  256u
#define OFF_P  4352u
#define PBUF   8192u
#define OFF_K  20736u
#define KBUF   4096u
#define OFF_V  28928u
#define VBUF   32768u
#define ATTN_SMEM (OFF_V + 2*VBUF)   // 94464 bytes -> 2 CTAs/SM

// copy V(jv) into vbuf (if jv valid) and K(jk) into kbuf (if jk valid)
__device__ __forceinline__ void copy_v(uint32_t vb, int t, int b, int j0)
{
    const __nv_bfloat16* src = g_hT + (size_t)t*TOTPIX + (b*NPIX + j0);
    #pragma unroll
    for (int c = 0; c < 8; c++)
        cpa16(vb + t*128 + ((c*16) ^ ((t&7)<<4)), src + c*8);
}
__device__ __forceinline__ void copy_k(uint32_t kb, int t, int b, int j0)
{
    const int j = t >> 2, c = t & 3;
    cpa16(kb + (j>>1)*128 + (j&1)*64 + c*16,
          g_k + (size_t)(b*NPIX + j0 + j)*CK + c*8);
}

// S(n) -> exp -> stsm into P[n&1]; accumulates lr
__device__ __forceinline__ void s_phase(uint32_t smb, int n,
                                        const uint32_t aq[2][2][4],
                                        int rs, int cg, int lane, float* lr)
{
    const uint32_t kb = smb + OFF_K + (uint32_t)(n & 1)*KBUF;
    const uint32_t pb = smb + OFF_P + (uint32_t)(n & 1)*PBUF;
    uint32_t KB[2][4];
    #pragma unroll
    for (int k16 = 0; k16 < 2; k16++)
        ldsm4(addrB_pk(kb, cg*16, k16*32, lane), KB[k16]);
    #pragma unroll
    for (int m = 0; m < 2; m++) {
        float s[2][4];
        #pragma unroll
        for (int nn = 0; nn < 2; nn++)
            { s[nn][0]=0.f; s[nn][1]=0.f; s[nn][2]=0.f; s[nn][3]=0.f; }
        #pragma unroll
        for (int k16 = 0; k16 < 2; k16++) {
            mma_f16(s[0], aq[m][k16], KB[k16][0], KB[k16][1]);
            mma_f16(s[1], aq[m][k16], KB[k16][2], KB[k16][3]);
        }
        uint32_t P01[2], P23[2];
        #pragma unroll
        for (int nn = 0; nn < 2; nn++) {
            float e0 = ex2(s[nn][0]-SHIFT), e1 = ex2(s[nn][1]-SHIFT);
            float e2 = ex2(s[nn][2]-SHIFT), e3 = ex2(s[nn][3]-SHIFT);
            lr[2*m]   += e0 + e1;
            lr[2*m+1] += e2 + e3;
            P01[nn] = bf2u32(e0, e1);
            P23[nn] = bf2u32(e2, e3);
        }
        stsm4(addrA(pb, rs + 16*m, cg*32, 128, lane),
              P01[0], P23[0], P01[1], P23[1]);
    }
}

__global__ __launch_bounds__(256, 2) void attn_kernel(
    const float* __restrict__ x,
    const float* __restrict__ gamma_p,
    float* __restrict__ out)
{
    extern __shared__ char sm[];
    const uint32_t smb = smem_u32(sm);
    float* ls = (float*)(sm + OFF_LS);

    const int t = threadIdx.x;
    const int w = t >> 5;
    const int lane = t & 31;
    const int b = blockIdx.y;
    const int q0 = blockIdx.x * 64;
    const size_t rowb = (size_t)(b*NPIX + q0);

    const int rs = (w & 1) * 32;     // rowgroup
    const int cg = w >> 1;           // colgroup (S 16-col slice / PV 64-d quarter)
    const int dh = cg * 64;

    if (t < 64) ls[t] = 0.f;

    // prologue: group0 = {Q, K(0), V(0)}, group1 = {K(1)}
    {
        const int j = t >> 2, c = t & 3;
        cpa16(smb + OFF_Q + (j>>1)*128 + (j&1)*64 + c*16,
              g_q + (rowb + j)*CK + c*8);
    }
    copy_k(smb + OFF_K, t, b, 0);
    copy_v(smb + OFF_V, t, b, 0);
    CPA_COMMIT();
    copy_k(smb + OFF_K + KBUF, t, b, JT);
    CPA_COMMIT();
    CPA_WAIT(1);          // Q + K(0) + V(0) ready
    __syncthreads();

    uint32_t aq[2][2][4];
    #pragma unroll
    for (int m = 0; m < 2; m++)
        #pragma unroll
        for (int kk = 0; kk < 2; kk++)
            ldsm4(addrA_pk(smb + OFF_Q, rs + 16*m, kk*32, lane), aq[m][kk]);

    float o[2][8][4];
    #pragma unroll
    for (int m = 0; m < 2; m++)
        #pragma unroll
        for (int n = 0; n < 8; n++)
            { o[m][n][0]=0.f; o[m][n][1]=0.f; o[m][n][2]=0.f; o[m][n][3]=0.f; }
    float lr[4] = {0.f, 0.f, 0.f, 0.f};

    // S(0) -> P[0]
    s_phase(smb, 0, aq, rs, cg, lane, lr);

    for (int it = 0; it < NIT; it++) {
        CPA_WAIT(0);       // group(it-1) = {V(it), K(it+1)} complete
        __syncthreads();   // reads of overwritten bufs done; P(it) visible

        // prefetch: V(it+1) -> buf (it+1)&1, K(it+2) -> buf it&1
        if (it + 1 < NIT) copy_v(smb + OFF_V + (uint32_t)((it+1)&1)*VBUF, t, b, (it+1)*JT);
        if (it + 2 < NIT) copy_k(smb + OFF_K + (uint32_t)(it&1)*KBUF, t, b, (it+2)*JT);
        CPA_COMMIT();

        // ---- S(it+1) -> P[(it+1)&1]  (independent of PV below) ----
        if (it + 1 < NIT)
            s_phase(smb, it+1, aq, rs, cg, lane, lr);

        // ---- PV(it): rows rs..rs+31 x d-quarter, k = JT ----
        const uint32_t pb = smb + OFF_P + (uint32_t)(it & 1)*PBUF;
        const uint32_t vb = smb + OFF_V + (uint32_t)(it & 1)*VBUF;
        #pragma unroll
        for (int j16 = 0; j16 < 4; j16++) {
            uint32_t A0[4], A1[4];
            ldsm4(addrA(pb, rs,      j16*32, 128, lane), A0);
            ldsm4(addrA(pb, rs + 16, j16*32, 128, lane), A1);
            #pragma unroll
            for (int n16 = 0; n16 < 4; n16++) {
                uint32_t Bv[4];
                ldsm4(addrB(vb, dh + n16*16, j16*32, 128, lane), Bv);
                mma_bf16(o[0][n16*2],   A0, Bv[0], Bv[1]);
                mma_bf16(o[0][n16*2+1], A0, Bv[2], Bv[3]);
                mma_bf16(o[1][n16*2],   A1, Bv[0], Bv[1]);
                mma_bf16(o[1][n16*2+1], A1, Bv[2], Bv[3]);
            }
        }
    }

    // ---- row sums: quad shuffles then cross-colgroup smem atomics ----
    #pragma unroll
    for (int i = 0; i < 4; i++) {
        lr[i] += __shfl_xor_sync(0xffffffffu, lr[i], 1);
        lr[i] += __shfl_xor_sync(0xffffffffu, lr[i], 2);
    }
    if ((lane & 3) == 0) {
        const int r = rs + (lane >> 2);
        atomicAdd(&ls[r],      lr[0]);
        atomicAdd(&ls[r + 8],  lr[1]);
        atomicAdd(&ls[r + 16], lr[2]);
        atomicAdd(&ls[r + 24], lr[3]);
    }
    __syncthreads();

    // ---- epilogue: y = gamma * O/l + x ----
    const float gamma = *gamma_p;
    #pragma unroll
    for (int m = 0; m < 2; m++) {
        const int ra = rs + 16*m + (lane >> 2);
        const int rb2 = ra + 8;
        const float ga = gamma / ls[ra];
        const float gb = gamma / ls[rb2];
        #pragma unroll
        for (int n = 0; n < 8; n++) {
            const float* oo = o[m][n];
            const int d = dh + (n>>1)*16 + (n&1)*8 + (lane & 3)*2;
            const size_t ea = (rowb + ra)*CDIM + d;
            const size_t eb = (rowb + rb2)*CDIM + d;
            float2 xa = *(const float2*)(x + ea);
            float2 xb = *(const float2*)(x + eb);
            float2 ya, yb;
            ya.x = fmaf(ga, oo[0], xa.x);
            ya.y = fmaf(ga, oo[1], xa.y);
            yb.x = fmaf(gb, oo[2], xb.x);
            yb.y = fmaf(gb, oo[3], xb.y);
            *(float2*)(out + ea) = ya;
            *(float2*)(out + eb) = yb;
        }
    }
}

// ============================================================================
extern "C" void kernel_launch(void* const* d_in, const int* in_sizes, int n_in,
                              void* d_out, int out_size)
{
    const float* x     = (const float*)d_in[0];
    const float* Wf    = (const float*)d_in[1];
    const float* bf    = (const float*)d_in[2];
    const float* Wg    = (const float*)d_in[3];
    const float* bg    = (const float*)d_in[4];
    const float* Wh    = (const float*)d_in[5];
    const float* bh    = (const float*)d_in[6];
    const float* gamma = (const float*)d_in[7];
    float* out = (float*)d_out;
    (void)in_sizes; (void)n_in; (void)out_size;

    cudaFuncSetAttribute(attn_kernel,
                         cudaFuncAttributeMaxDynamicSharedMemorySize, ATTN_SMEM);
    cudaFuncSetAttribute(proj_kernel,
                         cudaFuncAttributeMaxDynamicSharedMemorySize, PJ_SMEM);

    wsplit_kernel<<<320, 256>>>(Wf, Wg, Wh);
    xsplit_kernel<<<TOTPIX*32/256, 256>>>(x);
    proj_kernel<<<dim3(TOTPIX/128, 5), 256, PJ_SMEM>>>(bf, bg, bh);
    attn_kernel<<<dim3(NPIX/64, NB), 256, ATTN_SMEM>>>(x, gamma, out);
}

// round 11
// speedup vs baseline: 1.2909x; 1.2909x over previous
#include <cuda_runtime.h>
#include <cuda_bf16.h>
#include <cuda_fp16.h>
#include <cstdint>

#define NB 4
#define NPIX 4096
#define CDIM 256
#define CK 32
#define TOTPIX (NB*NPIX)
#define LOG2E 1.4426950408889634f
#define SHIFT 28.853900817779268f   // 20 * log2(e)

__device__ __half g_k[TOTPIX*CK];                   // keys fp16
__device__ __half g_q[TOTPIX*CK];                   // queries fp16, pre-scaled log2e
__device__ __nv_bfloat16 g_hT[(size_t)CDIM*TOTPIX]; // values bf16, channel-major
__device__ __nv_bfloat16 g_xs[(size_t)TOTPIX*512];  // [px][ xh(256) | xl(256) ]
__device__ __nv_bfloat16 g_wT[320*768];             // [col][ Whi | Whi | Wlo ]

__device__ __forceinline__ uint32_t bf2u32(float a, float b) {
    __nv_bfloat162 h = __floats2bfloat162_rn(a, b);
    return *reinterpret_cast<uint32_t*>(&h);
}
__device__ __forceinline__ void split_bf16(float v, __nv_bfloat16& hi, __nv_bfloat16& lo) {
    hi = __float2bfloat16_rn(v);
    lo = __float2bfloat16_rn(v - __bfloat162float(hi));
}
__device__ __forceinline__ uint32_t smem_u32(const void* p) {
    uint32_t r;
    asm("{ .reg .u64 t; cvta.to.shared.u64 t, %1; cvt.u32.u64 %0, t; }" : "=r"(r) : "l"(p));
    return r;
}
__device__ __forceinline__ float ex2(float x) {
    float y; asm("ex2.approx.f32 %0,%1;" : "=f"(y) : "f"(x)); return y;
}
__device__ __forceinline__ void mma_bf16(float* c, const uint32_t* a, uint32_t b0, uint32_t b1) {
    asm volatile(
        "mma.sync.aligned.m16n8k16.row.col.f32.bf16.bf16.f32 "
        "{%0,%1,%2,%3},{%4,%5,%6,%7},{%8,%9},{%0,%1,%2,%3};"
        : "+f"(c[0]), "+f"(c[1]), "+f"(c[2]), "+f"(c[3])
        : "r"(a[0]), "r"(a[1]), "r"(a[2]), "r"(a[3]), "r"(b0), "r"(b1));
}
__device__ __forceinline__ void mma_f16(float* c, const uint32_t* a, uint32_t b0, uint32_t b1) {
    asm volatile(
        "mma.sync.aligned.m16n8k16.row.col.f32.f16.f16.f32 "
        "{%0,%1,%2,%3},{%4,%5,%6,%7},{%8,%9},{%0,%1,%2,%3};"
        : "+f"(c[0]), "+f"(c[1]), "+f"(c[2]), "+f"(c[3])
        : "r"(a[0]), "r"(a[1]), "r"(a[2]), "r"(a[3]), "r"(b0), "r"(b1));
}
__device__ __forceinline__ void ldsm4(uint32_t addr, uint32_t* r) {
    asm volatile("ldmatrix.sync.aligned.m8n8.x4.shared.b16 {%0,%1,%2,%3},[%4];"
        : "=r"(r[0]), "=r"(r[1]), "=r"(r[2]), "=r"(r[3]) : "r"(addr));
}
__device__ __forceinline__ void stsm4(uint32_t addr, uint32_t r0, uint32_t r1,
                                      uint32_t r2, uint32_t r3) {
    asm volatile("stmatrix.sync.aligned.m8n8.x4.shared.b16 [%0], {%1,%2,%3,%4};"
        :: "r"(addr), "r"(r0), "r"(r1), "r"(r2), "r"(r3) : "memory");
}
__device__ __forceinline__ void cpa16(uint32_t dst, const void* src) {
    asm volatile("cp.async.cg.shared.global [%0],[%1],16;" :: "r"(dst), "l"(src) : "memory");
}
#define CPA_COMMIT() asm volatile("cp.async.commit_group;" ::: "memory")
#define CPA_WAIT(n)  asm volatile("cp.async.wait_group %0;" :: "n"(n) : "memory")

// swizzled layouts (stride = row bytes; swizzle bits [4:6] by row&7)
__device__ __forceinline__ uint32_t addrA(uint32_t base, int rbase, int kb, int stride, int lane) {
    int g = lane >> 3, lr = lane & 7;
    int r = rbase + lr + (g & 1) * 8;
    int kk = kb + (g & 2) * 8;
    return base + r * stride + (kk ^ ((r & 7) << 4));
}
__device__ __forceinline__ uint32_t addrB(uint32_t base, int rbase, int kb, int stride, int lane) {
    int g = lane >> 3, lr = lane & 7;
    int r = rbase + lr + (g & 2) * 4;
    int kk = kb + (g & 1) * 16;
    return base + r * stride + (kk ^ ((r & 7) << 4));
}
// packed 64B-rows (2 rows per 128B frame) layouts (Q, K) -- conflict-free
__device__ __forceinline__ uint32_t addrA_pk(uint32_t base, int rbase, int kb, int lane) {
    int g = lane >> 3, lr = lane & 7;
    int r = rbase + lr + (g & 1) * 8;
    int kk = kb + (g & 2) * 8;
    return base + (r >> 1)*128 + (r & 1)*64 + kk;
}
__device__ __forceinline__ uint32_t addrB_pk(uint32_t base, int rbase, int kb, int lane) {
    int g = lane >> 3, lr = lane & 7;
    int r = rbase + lr + (g & 2) * 4;
    int kk = kb + (g & 1) * 16;
    return base + (r >> 1)*128 + (r & 1)*64 + kk;
}

// ============================================================================
// Pre-kernel A: weight transpose/split -> g_wT[col][768]
// ============================================================================
__global__ __launch_bounds__(256) void wsplit_kernel(
    const float* __restrict__ Wf, const float* __restrict__ Wg,
    const float* __restrict__ Wh)
{
    const int col = blockIdx.x;
    const int k = threadIdx.x;
    float w;
    if (col < 256)      w = Wh[k*256 + col];
    else if (col < 288) w = Wf[k*32 + (col-256)];
    else                w = Wg[k*32 + (col-288)] * LOG2E;
    __nv_bfloat16 hi, lo;
    split_bf16(w, hi, lo);
    g_wT[col*768 + k]       = hi;
    g_wT[col*768 + 256 + k] = hi;
    g_wT[col*768 + 512 + k] = lo;
}

// ============================================================================
// Pre-kernel B: x hi/lo split -> g_xs[px][xh|xl]
// ============================================================================
__global__ __launch_bounds__(256) void xsplit_kernel(const float* __restrict__ x)
{
    const int gid = blockIdx.x * 256 + threadIdx.x;
    const int px = gid >> 5;
    const int seg = (gid & 31) * 8;
    float4 v0 = *(const float4*)(x + (size_t)px*256 + seg);
    float4 v1 = *(const float4*)(x + (size_t)px*256 + seg + 4);
    float vv[8] = {v0.x,v0.y,v0.z,v0.w,v1.x,v1.y,v1.z,v1.w};
    uint32_t H[4], L[4];
    #pragma unroll
    for (int i = 0; i < 4; i++) {
        __nv_bfloat16 h0,l0,h1,l1;
        split_bf16(vv[2*i],   h0, l0);
        split_bf16(vv[2*i+1], h1, l1);
        H[i] = (*(uint16_t*)&h0) | ((uint32_t)(*(uint16_t*)&h1) << 16);
        L[i] = (*(uint16_t*)&l0) | ((uint32_t)(*(uint16_t*)&l1) << 16);
    }
    *(uint4*)(g_xs + (size_t)px*512 + seg)       = make_uint4(H[0],H[1],H[2],H[3]);
    *(uint4*)(g_xs + (size_t)px*512 + 256 + seg) = make_uint4(L[0],L[1],L[2],L[3]);
}

// ============================================================================
// Projection GEMM: C[16384,320] = [xh|xl|xh] @ g_wT^T, K=768, 6 chunks.
// ============================================================================
#define PJ_AB   32768u
#define PJ_BB   16384u
#define PJ_SMEM (2*PJ_AB + 2*PJ_BB)

__device__ __forceinline__ void pj_copy(uint32_t smb, int t, int rows0, int c0, int n)
{
    static const int kxb[6] = {0,128,256,384,0,128};
    const uint32_t ab = smb + (uint32_t)(n & 1)*PJ_AB;
    const uint32_t bb = smb + 2*PJ_AB + (uint32_t)(n & 1)*PJ_BB;
    {
        const int r = t >> 1, half = t & 1;
        const __nv_bfloat16* src = g_xs + (size_t)(rows0 + r)*512 + kxb[n];
        #pragma unroll
        for (int i = 0; i < 8; i++) {
            int p = half*8 + i;
            cpa16(ab + r*256 + ((p*16) ^ ((r & 7) << 4)), src + p*8);
        }
    }
    {
        const int c = t >> 2, q = t & 3;
        const __nv_bfloat16* src = g_wT + (size_t)(c0 + c)*768 + n*128;
        #pragma unroll
        for (int i = 0; i < 4; i++) {
            int p = q*4 + i;
            cpa16(bb + c*256 + ((p*16) ^ ((c & 7) << 4)), src + p*8);
        }
    }
}

__global__ __launch_bounds__(256, 2) void proj_kernel(
    const float* __restrict__ bfp, const float* __restrict__ bgp,
    const float* __restrict__ bhp)
{
    extern __shared__ char sm[];
    const uint32_t smb = smem_u32(sm);
    const int t = threadIdx.x;
    const int w = t >> 5;
    const int lane = t & 31;
    const int rows0 = blockIdx.x * 128;
    const int c0 = blockIdx.y * 64;
    const int rs = (w & 3) * 32;
    const int cs = (w >> 2) * 32;

    float acc[2][4][4];
    #pragma unroll
    for (int m = 0; m < 2; m++)
        #pragma unroll
        for (int n = 0; n < 4; n++)
            { acc[m][n][0]=0.f; acc[m][n][1]=0.f; acc[m][n][2]=0.f; acc[m][n][3]=0.f; }

    pj_copy(smb, t, rows0, c0, 0);
    CPA_COMMIT();

    for (int n = 0; n < 6; n++) {
        if (n + 1 < 6) {
            pj_copy(smb, t, rows0, c0, n+1);
            CPA_COMMIT();
            CPA_WAIT(1);
        } else {
            CPA_WAIT(0);
        }
        __syncthreads();
        const uint32_t ab = smb + (uint32_t)(n & 1)*PJ_AB;
        const uint32_t bb = smb + 2*PJ_AB + (uint32_t)(n & 1)*PJ_BB;
        #pragma unroll
        for (int k16 = 0; k16 < 8; k16++) {
            uint32_t a0[4], a1[4];
            ldsm4(addrA(ab, rs,      k16*32, 256, lane), a0);
            ldsm4(addrA(ab, rs + 16, k16*32, 256, lane), a1);
            #pragma unroll
            for (int n16 = 0; n16 < 2; n16++) {
                uint32_t B[4];
                ldsm4(addrB(bb, cs + n16*16, k16*32, 256, lane), B);
                mma_bf16(acc[0][n16*2],   a0, B[0], B[1]);
                mma_bf16(acc[0][n16*2+1], a0, B[2], B[3]);
                mma_bf16(acc[1][n16*2],   a1, B[0], B[1]);
                mma_bf16(acc[1][n16*2+1], a1, B[2], B[3]);
            }
        }
        __syncthreads();
    }

    #pragma unroll
    for (int n = 0; n < 4; n++) {
        const int cA = cs + n*8 + (lane & 3)*2;
        #pragma unroll
        for (int half = 0; half < 2; half++) {
            const int gc = c0 + cA + half;
            float bias;
            if (gc < 256)      bias = bhp[gc];
            else if (gc < 288) bias = bfp[gc-256];
            else               bias = bgp[gc-288] * LOG2E;
            #pragma unroll
            for (int m = 0; m < 2; m++) {
                #pragma unroll
                for (int eh = 0; eh < 2; eh++) {
                    const int r = rs + m*16 + (lane >> 2) + eh*8;
                    const int px = rows0 + r;
                    float v = acc[m][n][eh*2 + half] + bias;
                    if (gc < 256) {
                        g_hT[(size_t)gc*TOTPIX + px] = __float2bfloat16_rn(v);
                    } else if (gc < 288) {
                        g_k[(size_t)px*CK + (gc-256)] = __float2half_rn(v);
                    } else {
                        g_q[(size_t)px*CK + (gc-288)] = __float2half_rn(v);
                    }
                }
            }
        }
    }
}

// ============================================================================
// Flash attention, split-d: CTA = 128 queries x 128-d half, 256 thr (8 warps),
// 2 CTAs/SM. Both d-half CTAs recompute S/exp (cheap); V copy traffic per SM
// stays equal to the 512-thr version. 3-deep K/V, double P, 1 barrier/iter.
//   warp (rg = w&3: 32 q-rows) x (cg = w>>2: 32 S-cols / 64-d quarter of half)
// ============================================================================
#define JT 64
#define NIT (NPIX/JT)
#define OFF_LS 0u
#define OFF_Q  512u
#define OFF_P  8704u
#define PBUF   16384u
#define OFF_K  41472u
#define KBUF   4096u
#define OFF_V  53760u
#define VBUF   16384u
#define ATTN_SMEM (OFF_V + 3*VBUF)   // 102912 bytes -> 2 CTAs/SM

__device__ __forceinline__ void copy_kv(uint32_t kb, uint32_t vb,
                                        int t, int b, int dh0, int j0)
{
    { // K tile: 64 rows x 64B packed 2/frame (256 cpa16)
        const int j = t >> 2, c = t & 3;
        cpa16(kb + (j>>1)*128 + (j&1)*64 + c*16,
              g_k + (size_t)(b*NPIX + j0 + j)*CK + c*8);
    }
    { // V half-tile: 128 d-rows x 128B swizzled (1024 cpa16)
        const int dd = t >> 1;
        const __nv_bfloat16* src = g_hT + (size_t)(dh0 + dd)*TOTPIX + (b*NPIX + j0);
        #pragma unroll
        for (int i = 0; i < 4; i++) {
            int c = (t & 1)*4 + i;
            cpa16(vb + dd*128 + ((c*16) ^ ((dd&7)<<4)), src + c*8);
        }
    }
}

// S(n) over warp's 32 cols -> exp -> stsm into P[n&1]; accumulates lr
__device__ __forceinline__ void s_phase(uint32_t smb, int n,
                                        const uint32_t aq[2][2][4],
                                        int rs, int cs, int lane, float* lr)
{
    const uint32_t kb = smb + OFF_K + (uint32_t)(n % 3)*KBUF;
    const uint32_t pb = smb + OFF_P + (uint32_t)(n & 1)*PBUF;
    uint32_t KB[2][2][4];   // [n16][k16]
    #pragma unroll
    for (int n16 = 0; n16 < 2; n16++)
        #pragma unroll
        for (int k16 = 0; k16 < 2; k16++)
            ldsm4(addrB_pk(kb, cs + n16*16, k16*32, lane), KB[n16][k16]);

    #pragma unroll
    for (int m = 0; m < 2; m++) {
        float s[4][4];
        #pragma unroll
        for (int nn = 0; nn < 4; nn++)
            { s[nn][0]=0.f; s[nn][1]=0.f; s[nn][2]=0.f; s[nn][3]=0.f; }
        #pragma unroll
        for (int k16 = 0; k16 < 2; k16++) {
            mma_f16(s[0], aq[m][k16], KB[0][k16][0], KB[0][k16][1]);
            mma_f16(s[1], aq[m][k16], KB[0][k16][2], KB[0][k16][3]);
            mma_f16(s[2], aq[m][k16], KB[1][k16][0], KB[1][k16][1]);
            mma_f16(s[3], aq[m][k16], KB[1][k16][2], KB[1][k16][3]);
        }
        #pragma unroll
        for (int n16 = 0; n16 < 2; n16++) {
            uint32_t P01[2], P23[2];
            #pragma unroll
            for (int nn = 0; nn < 2; nn++) {
                const float* sv = s[n16*2 + nn];
                float e0 = ex2(sv[0]-SHIFT), e1 = ex2(sv[1]-SHIFT);
                float e2 = ex2(sv[2]-SHIFT), e3 = ex2(sv[3]-SHIFT);
                lr[2*m]   += e0 + e1;
                lr[2*m+1] += e2 + e3;
                P01[nn] = bf2u32(e0, e1);
                P23[nn] = bf2u32(e2, e3);
            }
            stsm4(addrA(pb, rs + 16*m, (cs + n16*16)*2, 128, lane),
                  P01[0], P23[0], P01[1], P23[1]);
        }
    }
}

__global__ __launch_bounds__(256, 2) void attn_kernel(
    const float* __restrict__ x,
    const float* __restrict__ gamma_p,
    float* __restrict__ out)
{
    extern __shared__ char sm[];
    const uint32_t smb = smem_u32(sm);
    float* ls = (float*)(sm + OFF_LS);

    const int t = threadIdx.x;
    const int w = t >> 5;
    const int lane = t & 31;
    const int b = blockIdx.y;
    const int dh0 = blockIdx.z * 128;        // this CTA's global d-half base
    const int q0 = blockIdx.x * 128;
    const size_t rowb = (size_t)(b*NPIX + q0);

    const int rs = (w & 3) * 32;             // rowgroup
    const int cg = w >> 2;                   // colgroup (0/1)
    const int cs = cg * 32;                  // S col base (32 cols/warp)
    const int dq = cg * 64;                  // PV d-quarter base (local to half)

    if (t < 128) ls[t] = 0.f;

    // prologue: group0 = {Q, K(0), V(0)}, group1 = {K(1), V(1)}
    {   // Q: 128 rows x 64B packed (512 cpa16, 2 per thread)
        const int j = t >> 1;
        const __half* src = g_q + (rowb + j)*CK;
        #pragma unroll
        for (int i = 0; i < 2; i++) {
            int c = (t & 1)*2 + i;
            cpa16(smb + OFF_Q + (j>>1)*128 + (j&1)*64 + c*16, src + c*8);
        }
    }
    copy_kv(smb + OFF_K, smb + OFF_V, t, b, dh0, 0);
    CPA_COMMIT();
    copy_kv(smb + OFF_K + KBUF, smb + OFF_V + VBUF, t, b, dh0, JT);
    CPA_COMMIT();
    CPA_WAIT(1);          // Q + K(0) + V(0) ready
    __syncthreads();

    uint32_t aq[2][2][4];
    #pragma unroll
    for (int m = 0; m < 2; m++)
        #pragma unroll
        for (int kk = 0; kk < 2; kk++)
            ldsm4(addrA_pk(smb + OFF_Q, rs + 16*m, kk*32, lane), aq[m][kk]);

    float o[2][8][4];
    #pragma unroll
    for (int m = 0; m < 2; m++)
        #pragma unroll
        for (int n = 0; n < 8; n++)
            { o[m][n][0]=0.f; o[m][n][1]=0.f; o[m][n][2]=0.f; o[m][n][3]=0.f; }
    float lr[4] = {0.f, 0.f, 0.f, 0.f};

    // S(0) -> P[0]
    s_phase(smb, 0, aq, rs, cs, lane, lr);

    for (int it = 0; it < NIT; it++) {
        CPA_WAIT(0);       // K/V(it+1) complete
        __syncthreads();   // PV(it-1)/S(it) reads done; copies + P(it) visible

        if (it + 2 < NIT) {   // prefetch K/V(it+2): buffers free (3-deep)
            copy_kv(smb + OFF_K + (uint32_t)((it+2)%3)*KBUF,
                    smb + OFF_V + (uint32_t)((it+2)%3)*VBUF, t, b, dh0, (it+2)*JT);
            CPA_COMMIT();
        }

        // ---- S(it+1) -> P[(it+1)&1]  (independent of PV below) ----
        if (it + 1 < NIT)
            s_phase(smb, it+1, aq, rs, cs, lane, lr);

        // ---- PV(it): rows rs..rs+31 x 64-d quarter of this half, k = JT ----
        const uint32_t pb = smb + OFF_P + (uint32_t)(it & 1)*PBUF;
        const uint32_t vb = smb + OFF_V + (uint32_t)(it % 3)*VBUF;
        #pragma unroll
        for (int j16 = 0; j16 < 4; j16++) {
            uint32_t A0[4], A1[4];
            ldsm4(addrA(pb, rs,      j16*32, 128, lane), A0);
            ldsm4(addrA(pb, rs + 16, j16*32, 128, lane), A1);
            #pragma unroll
            for (int n16 = 0; n16 < 4; n16++) {
                uint32_t Bv[4];
                ldsm4(addrB(vb, dq + n16*16, j16*32, 128, lane), Bv);
                mma_bf16(o[0][n16*2],   A0, Bv[0], Bv[1]);
                mma_bf16(o[0][n16*2+1], A0, Bv[2], Bv[3]);
                mma_bf16(o[1][n16*2],   A1, Bv[0], Bv[1]);
                mma_bf16(o[1][n16*2+1], A1, Bv[2], Bv[3]);
            }
        }
    }

    // ---- row sums: quad shuffles then cross-colgroup smem atomics ----
    #pragma unroll
    for (int i = 0; i < 4; i++) {
        lr[i] += __shfl_xor_sync(0xffffffffu, lr[i], 1);
        lr[i] += __shfl_xor_sync(0xffffffffu, lr[i], 2);
    }
    if ((lane & 3) == 0) {
        const int r = rs + (lane >> 2);
        atomicAdd(&ls[r],      lr[0]);
        atomicAdd(&ls[r + 8],  lr[1]);
        atomicAdd(&ls[r + 16], lr[2]);
        atomicAdd(&ls[r + 24], lr[3]);
    }
    __syncthreads();

    // ---- epilogue: y = gamma * O/l + x  (this CTA writes its d-half only) ----
    const float gamma = *gamma_p;
    #pragma unroll
    for (int m = 0; m < 2; m++) {
        const int ra = rs + 16*m + (lane >> 2);
        const int rb2 = ra + 8;
        const float ga = gamma / ls[ra];
        const float gb = gamma / ls[rb2];
        #pragma unroll
        for (int n = 0; n < 8; n++) {
            const float* oo = o[m][n];
            const int d = dh0 + dq + (n>>1)*16 + (n&1)*8 + (lane & 3)*2;
            const size_t ea = (rowb + ra)*CDIM + d;
            const size_t eb = (rowb + rb2)*CDIM + d;
            float2 xa = *(const float2*)(x + ea);
            float2 xb = *(const float2*)(x + eb);
            float2 ya, yb;
            ya.x = fmaf(ga, oo[0], xa.x);
            ya.y = fmaf(ga, oo[1], xa.y);
            yb.x = fmaf(gb, oo[2], xb.x);
            yb.y = fmaf(gb, oo[3], xb.y);
            *(float2*)(out + ea) = ya;
            *(float2*)(out + eb) = yb;
        }
    }
}

// ============================================================================
extern "C" void kernel_launch(void* const* d_in, const int* in_sizes, int n_in,
                              void* d_out, int out_size)
{
    const float* x     = (const float*)d_in[0];
    const float* Wf    = (const float*)d_in[1];
    const float* bf    = (const float*)d_in[2];
    const float* Wg    = (const float*)d_in[3];
    const float* bg    = (const float*)d_in[4];
    const float* Wh    = (const float*)d_in[5];
    const float* bh    = (const float*)d_in[6];
    const float* gamma = (const float*)d_in[7];
    float* out = (float*)d_out;
    (void)in_sizes; (void)n_in; (void)out_size;

    cudaFuncSetAttribute(attn_kernel,
                         cudaFuncAttributeMaxDynamicSharedMemorySize, ATTN_SMEM);
    cudaFuncSetAttribute(proj_kernel,
                         cudaFuncAttributeMaxDynamicSharedMemorySize, PJ_SMEM);

    wsplit_kernel<<<320, 256>>>(Wf, Wg, Wh);
    xsplit_kernel<<<TOTPIX*32/256, 256>>>(x);
    proj_kernel<<<dim3(TOTPIX/128, 5), 256, PJ_SMEM>>>(bf, bg, bh);
    attn_kernel<<<dim3(NPIX/128, NB, 2), 256, ATTN_SMEM>>>(x, gamma, out);
}

// round 12
// speedup vs baseline: 1.7957x; 1.3911x over previous
#include <cuda_runtime.h>
#include <cuda_bf16.h>
#include <cuda_fp16.h>
#include <cstdint>

#define NB 4
#define NPIX 4096
#define CDIM 256
#define CK 32
#define TOTPIX (NB*NPIX)
#define LOG2E 1.4426950408889634f
#define SHIFT 28.853900817779268f   // 20 * log2(e)

__device__ __half g_k[TOTPIX*CK];                   // keys fp16
__device__ __half g_q[TOTPIX*CK];                   // queries fp16, pre-scaled log2e
__device__ __nv_bfloat16 g_hT[(size_t)CDIM*TOTPIX]; // values bf16, channel-major
__device__ __half g_xh[(size_t)TOTPIX*CDIM];        // x as fp16 [px][256]
__device__ __half g_wT[320*CDIM];                   // [col][256] fp16 (Wg pre-scaled)

__device__ __forceinline__ uint32_t bf2u32(float a, float b) {
    __nv_bfloat162 h = __floats2bfloat162_rn(a, b);
    return *reinterpret_cast<uint32_t*>(&h);
}
__device__ __forceinline__ uint32_t smem_u32(const void* p) {
    uint32_t r;
    asm("{ .reg .u64 t; cvta.to.shared.u64 t, %1; cvt.u32.u64 %0, t; }" : "=r"(r) : "l"(p));
    return r;
}
__device__ __forceinline__ float ex2(float x) {
    float y; asm("ex2.approx.f32 %0,%1;" : "=f"(y) : "f"(x)); return y;
}
__device__ __forceinline__ void mma_bf16(float* c, const uint32_t* a, uint32_t b0, uint32_t b1) {
    asm volatile(
        "mma.sync.aligned.m16n8k16.row.col.f32.bf16.bf16.f32 "
        "{%0,%1,%2,%3},{%4,%5,%6,%7},{%8,%9},{%0,%1,%2,%3};"
        : "+f"(c[0]), "+f"(c[1]), "+f"(c[2]), "+f"(c[3])
        : "r"(a[0]), "r"(a[1]), "r"(a[2]), "r"(a[3]), "r"(b0), "r"(b1));
}
__device__ __forceinline__ void mma_f16(float* c, const uint32_t* a, uint32_t b0, uint32_t b1) {
    asm volatile(
        "mma.sync.aligned.m16n8k16.row.col.f32.f16.f16.f32 "
        "{%0,%1,%2,%3},{%4,%5,%6,%7},{%8,%9},{%0,%1,%2,%3};"
        : "+f"(c[0]), "+f"(c[1]), "+f"(c[2]), "+f"(c[3])
        : "r"(a[0]), "r"(a[1]), "r"(a[2]), "r"(a[3]), "r"(b0), "r"(b1));
}
__device__ __forceinline__ void ldsm4(uint32_t addr, uint32_t* r) {
    asm volatile("ldmatrix.sync.aligned.m8n8.x4.shared.b16 {%0,%1,%2,%3},[%4];"
        : "=r"(r[0]), "=r"(r[1]), "=r"(r[2]), "=r"(r[3]) : "r"(addr));
}
__device__ __forceinline__ void stsm4(uint32_t addr, uint32_t r0, uint32_t r1,
                                      uint32_t r2, uint32_t r3) {
    asm volatile("stmatrix.sync.aligned.m8n8.x4.shared.b16 [%0], {%1,%2,%3,%4};"
        :: "r"(addr), "r"(r0), "r"(r1), "r"(r2), "r"(r3) : "memory");
}
__device__ __forceinline__ void cpa16(uint32_t dst, const void* src) {
    asm volatile("cp.async.cg.shared.global [%0],[%1],16;" :: "r"(dst), "l"(src) : "memory");
}
#define CPA_COMMIT() asm volatile("cp.async.commit_group;" ::: "memory")
#define CPA_WAIT(n)  asm volatile("cp.async.wait_group %0;" :: "n"(n) : "memory")

// swizzled layouts (stride = row bytes; swizzle bits [4:6] by row&7)
__device__ __forceinline__ uint32_t addrA(uint32_t base, int rbase, int kb, int stride, int lane) {
    int g = lane >> 3, lr = lane & 7;
    int r = rbase + lr + (g & 1) * 8;
    int kk = kb + (g & 2) * 8;
    return base + r * stride + (kk ^ ((r & 7) << 4));
}
__device__ __forceinline__ uint32_t addrB(uint32_t base, int rbase, int kb, int stride, int lane) {
    int g = lane >> 3, lr = lane & 7;
    int r = rbase + lr + (g & 2) * 4;
    int kk = kb + (g & 1) * 16;
    return base + r * stride + (kk ^ ((r & 7) << 4));
}
// packed 64B-rows (2 rows per 128B frame) layouts (Q, K) -- conflict-free
__device__ __forceinline__ uint32_t addrA_pk(uint32_t base, int rbase, int kb, int lane) {
    int g = lane >> 3, lr = lane & 7;
    int r = rbase + lr + (g & 1) * 8;
    int kk = kb + (g & 2) * 8;
    return base + (r >> 1)*128 + (r & 1)*64 + kk;
}
__device__ __forceinline__ uint32_t addrB_pk(uint32_t base, int rbase, int kb, int lane) {
    int g = lane >> 3, lr = lane & 7;
    int r = rbase + lr + (g & 2) * 4;
    int kk = kb + (g & 1) * 16;
    return base + (r >> 1)*128 + (r & 1)*64 + kk;
}

// ============================================================================
// Pre-kernel A: weight transpose -> g_wT[col][256] fp16
//   col<256: Wh col; col<288: Wf col; else: Wg col * LOG2E
// ============================================================================
__global__ __launch_bounds__(256) void wsplit_kernel(
    const float* __restrict__ Wf, const float* __restrict__ Wg,
    const float* __restrict__ Wh)
{
    const int col = blockIdx.x;
    const int k = threadIdx.x;
    float w;
    if (col < 256)      w = Wh[k*256 + col];
    else if (col < 288) w = Wf[k*32 + (col-256)];
    else                w = Wg[k*32 + (col-288)] * LOG2E;
    g_wT[col*CDIM + k] = __float2half_rn(w);
}

// ============================================================================
// Pre-kernel B: x f32 -> fp16  g_xh[px][256]
// ============================================================================
__global__ __launch_bounds__(256) void xsplit_kernel(const float* __restrict__ x)
{
    const size_t gid = (size_t)blockIdx.x * 256 + threadIdx.x;   // one per 8 elems
    const float4 v0 = *(const float4*)(x + gid*8);
    const float4 v1 = *(const float4*)(x + gid*8 + 4);
    __half2 h[4];
    h[0] = __floats2half2_rn(v0.x, v0.y);
    h[1] = __floats2half2_rn(v0.z, v0.w);
    h[2] = __floats2half2_rn(v1.x, v1.y);
    h[3] = __floats2half2_rn(v1.z, v1.w);
    *(uint4*)(g_xh + gid*8) = *(const uint4*)h;
}

// ============================================================================
// Projection GEMM: C[16384,320] = x_f16 @ g_wT^T, K=256 in 2 chunks.
// Block = 128 px x 64 cols, 256 thr (8 warps, 32x32 warp tiles).
// ============================================================================
#define PJ_AB   32768u
#define PJ_BB   16384u
#define PJ_SMEM (2*PJ_AB + 2*PJ_BB)

__device__ __forceinline__ void pj_copy(uint32_t smb, int t, int rows0, int c0, int n)
{
    const uint32_t ab = smb + (uint32_t)(n & 1)*PJ_AB;
    const uint32_t bb = smb + 2*PJ_AB + (uint32_t)(n & 1)*PJ_BB;
    { // A: 128 rows x 256B (128 fp16 of this k-chunk)
        const int r = t >> 1, half = t & 1;
        const __half* src = g_xh + (size_t)(rows0 + r)*CDIM + n*128;
        #pragma unroll
        for (int i = 0; i < 8; i++) {
            int p = half*8 + i;
            cpa16(ab + r*256 + ((p*16) ^ ((r & 7) << 4)), src + p*8);
        }
    }
    { // B: 64 rows(cols) x 256B
        const int c = t >> 2, q = t & 3;
        const __half* src = g_wT + (size_t)(c0 + c)*CDIM + n*128;
        #pragma unroll
        for (int i = 0; i < 4; i++) {
            int p = q*4 + i;
            cpa16(bb + c*256 + ((p*16) ^ ((c & 7) << 4)), src + p*8);
        }
    }
}

__global__ __launch_bounds__(256, 2) void proj_kernel(
    const float* __restrict__ bfp, const float* __restrict__ bgp,
    const float* __restrict__ bhp)
{
    extern __shared__ char sm[];
    const uint32_t smb = smem_u32(sm);
    const int t = threadIdx.x;
    const int w = t >> 5;
    const int lane = t & 31;
    const int rows0 = blockIdx.x * 128;
    const int c0 = blockIdx.y * 64;
    const int rs = (w & 3) * 32;
    const int cs = (w >> 2) * 32;

    float acc[2][4][4];
    #pragma unroll
    for (int m = 0; m < 2; m++)
        #pragma unroll
        for (int n = 0; n < 4; n++)
            { acc[m][n][0]=0.f; acc[m][n][1]=0.f; acc[m][n][2]=0.f; acc[m][n][3]=0.f; }

    pj_copy(smb, t, rows0, c0, 0);
    CPA_COMMIT();
    pj_copy(smb, t, rows0, c0, 1);
    CPA_COMMIT();
    CPA_WAIT(1);
    __syncthreads();

    #pragma unroll
    for (int n = 0; n < 2; n++) {
        if (n == 1) { CPA_WAIT(0); __syncthreads(); }
        const uint32_t ab = smb + (uint32_t)(n & 1)*PJ_AB;
        const uint32_t bb = smb + 2*PJ_AB + (uint32_t)(n & 1)*PJ_BB;
        #pragma unroll
        for (int k16 = 0; k16 < 8; k16++) {
            uint32_t a0[4], a1[4];
            ldsm4(addrA(ab, rs,      k16*32, 256, lane), a0);
            ldsm4(addrA(ab, rs + 16, k16*32, 256, lane), a1);
            #pragma unroll
            for (int n16 = 0; n16 < 2; n16++) {
                uint32_t B[4];
                ldsm4(addrB(bb, cs + n16*16, k16*32, 256, lane), B);
                mma_f16(acc[0][n16*2],   a0, B[0], B[1]);
                mma_f16(acc[0][n16*2+1], a0, B[2], B[3]);
                mma_f16(acc[1][n16*2],   a1, B[0], B[1]);
                mma_f16(acc[1][n16*2+1], a1, B[2], B[3]);
            }
        }
    }

    // ---- epilogue ----
    #pragma unroll
    for (int n = 0; n < 4; n++) {
        const int cA = cs + n*8 + (lane & 3)*2;
        #pragma unroll
        for (int half = 0; half < 2; half++) {
            const int gc = c0 + cA + half;
            float bias;
            if (gc < 256)      bias = bhp[gc];
            else if (gc < 288) bias = bfp[gc-256];
            else               bias = bgp[gc-288] * LOG2E;
            #pragma unroll
            for (int m = 0; m < 2; m++) {
                #pragma unroll
                for (int eh = 0; eh < 2; eh++) {
                    const int r = rs + m*16 + (lane >> 2) + eh*8;
                    const int px = rows0 + r;
                    float v = acc[m][n][eh*2 + half] + bias;
                    if (gc < 256) {
                        g_hT[(size_t)gc*TOTPIX + px] = __float2bfloat16_rn(v);
                    } else if (gc < 288) {
                        g_k[(size_t)px*CK + (gc-256)] = __float2half_rn(v);
                    } else {
                        g_q[(size_t)px*CK + (gc-288)] = __float2half_rn(v);
                    }
                }
            }
        }
    }
}

// ============================================================================
// Flash attention (round-9 best): 16 warps, software-pipelined
// (S(it+1) overlaps PV(it)). j-tile 64, triple-buffered K/V, double P,
// ONE barrier per iter.
//   warp (rg = w&3: 32 q-rows) x (cg = w>>2: 16 S-cols / 64-d quarter)
// ============================================================================
#define JT 64
#define NIT (NPIX/JT)
#define OFF_LS 0u
#define OFF_Q  512u
#define OFF_P  8704u
#define PBUF   16384u
#define OFF_K  41472u
#define KBUF   4096u
#define OFF_V  53760u
#define VBUF   32768u
#define ATTN_SMEM (OFF_V + 3*VBUF)   // 152064

__device__ __forceinline__ void copy_kv(uint32_t kb, uint32_t vb,
                                        int t, int b, int j0)
{
    if (t < 256) { // K tile: 64 rows x 64B packed 2/frame
        const int j = t >> 2, c = t & 3;
        cpa16(kb + (j>>1)*128 + (j&1)*64 + c*16,
              g_k + (size_t)(b*NPIX + j0 + j)*CK + c*8);
    }
    { // V tile: 256 d-rows x 128B swizzled
        const int dd = t >> 1;
        const __nv_bfloat16* src = g_hT + (size_t)dd*TOTPIX + (b*NPIX + j0);
        #pragma unroll
        for (int i = 0; i < 4; i++) {
            int c = (t & 1)*4 + i;
            cpa16(vb + dd*128 + ((c*16) ^ ((dd&7)<<4)), src + c*8);
        }
    }
}

// S(n) -> exp -> stsm into P[n&1]; accumulates lr
__device__ __forceinline__ void s_phase(uint32_t smb, int n,
                                        const uint32_t aq[2][2][4],
                                        int rs, int cg, int lane, float* lr)
{
    const uint32_t kb = smb + OFF_K + (uint32_t)(n % 3)*KBUF;
    const uint32_t pb = smb + OFF_P + (uint32_t)(n & 1)*PBUF;
    uint32_t KB[2][4];
    #pragma unroll
    for (int k16 = 0; k16 < 2; k16++)
        ldsm4(addrB_pk(kb, cg*16, k16*32, lane), KB[k16]);
    #pragma unroll
    for (int m = 0; m < 2; m++) {
        float s[2][4];
        #pragma unroll
        for (int nn = 0; nn < 2; nn++)
            { s[nn][0]=0.f; s[nn][1]=0.f; s[nn][2]=0.f; s[nn][3]=0.f; }
        #pragma unroll
        for (int k16 = 0; k16 < 2; k16++) {
            mma_f16(s[0], aq[m][k16], KB[k16][0], KB[k16][1]);
            mma_f16(s[1], aq[m][k16], KB[k16][2], KB[k16][3]);
        }
        uint32_t P01[2], P23[2];
        #pragma unroll
        for (int nn = 0; nn < 2; nn++) {
            float e0 = ex2(s[nn][0]-SHIFT), e1 = ex2(s[nn][1]-SHIFT);
            float e2 = ex2(s[nn][2]-SHIFT), e3 = ex2(s[nn][3]-SHIFT);
            lr[2*m]   += e0 + e1;
            lr[2*m+1] += e2 + e3;
            P01[nn] = bf2u32(e0, e1);
            P23[nn] = bf2u32(e2, e3);
        }
        stsm4(addrA(pb, rs + 16*m, cg*32, 128, lane),
              P01[0], P23[0], P01[1], P23[1]);
    }
}

__global__ __launch_bounds__(512, 1) void attn_kernel(
    const float* __restrict__ x,
    const float* __restrict__ gamma_p,
    float* __restrict__ out)
{
    extern __shared__ char sm[];
    const uint32_t smb = smem_u32(sm);
    float* ls = (float*)(sm + OFF_LS);

    const int t = threadIdx.x;
    const int w = t >> 5;
    const int lane = t & 31;
    const int b = blockIdx.y;
    const int q0 = blockIdx.x * 128;
    const size_t rowb = (size_t)(b*NPIX + q0);

    const int rs = (w & 3) * 32;     // rowgroup
    const int cg = w >> 2;           // colgroup (S 16-col slice / PV 64-d quarter)
    const int dh = cg * 64;

    if (t < 128) ls[t] = 0.f;

    // prologue: group0 = {Q, K(0), V(0)}, group1 = {K(1), V(1)}
    {
        const int j = t >> 2, c = t & 3;
        cpa16(smb + OFF_Q + (j>>1)*128 + (j&1)*64 + c*16,
              g_q + (rowb + j)*CK + c*8);
    }
    copy_kv(smb + OFF_K, smb + OFF_V, t, b, 0);
    CPA_COMMIT();
    copy_kv(smb + OFF_K + KBUF, smb + OFF_V + VBUF, t, b, JT);
    CPA_COMMIT();
    CPA_WAIT(1);          // Q + K(0) + V(0) ready
    __syncthreads();

    uint32_t aq[2][2][4];
    #pragma unroll
    for (int m = 0; m < 2; m++)
        #pragma unroll
        for (int kk = 0; kk < 2; kk++)
            ldsm4(addrA_pk(smb + OFF_Q, rs + 16*m, kk*32, lane), aq[m][kk]);

    float o[2][8][4];
    #pragma unroll
    for (int m = 0; m < 2; m++)
        #pragma unroll
        for (int n = 0; n < 8; n++)
            { o[m][n][0]=0.f; o[m][n][1]=0.f; o[m][n][2]=0.f; o[m][n][3]=0.f; }
    float lr[4] = {0.f, 0.f, 0.f, 0.f};

    // S(0) -> P[0]
    s_phase(smb, 0, aq, rs, cg, lane, lr);

    for (int it = 0; it < NIT; it++) {
        CPA_WAIT(0);       // K/V(it+1) complete
        __syncthreads();   // PV(it-1)/S(it) reads done; copies + P(it) visible

        if (it + 2 < NIT) {   // prefetch K/V(it+2): buffers free (3-deep)
            copy_kv(smb + OFF_K + (uint32_t)((it+2)%3)*KBUF,
                    smb + OFF_V + (uint32_t)((it+2)%3)*VBUF, t, b, (it+2)*JT);
            CPA_COMMIT();
        }

        // ---- S(it+1) -> P[(it+1)&1]  (independent of PV below) ----
        if (it + 1 < NIT)
            s_phase(smb, it+1, aq, rs, cg, lane, lr);

        // ---- PV(it): rows rs..rs+31 x d-quarter, k = JT ----
        const uint32_t pb = smb + OFF_P + (uint32_t)(it & 1)*PBUF;
        const uint32_t vb = smb + OFF_V + (uint32_t)(it % 3)*VBUF;
        #pragma unroll
        for (int j16 = 0; j16 < 4; j16++) {
            uint32_t A0[4], A1[4];
            ldsm4(addrA(pb, rs,      j16*32, 128, lane), A0);
            ldsm4(addrA(pb, rs + 16, j16*32, 128, lane), A1);
            #pragma unroll
            for (int n16 = 0; n16 < 4; n16++) {
                uint32_t Bv[4];
                ldsm4(addrB(vb, dh + n16*16, j16*32, 128, lane), Bv);
                mma_bf16(o[0][n16*2],   A0, Bv[0], Bv[1]);
                mma_bf16(o[0][n16*2+1], A0, Bv[2], Bv[3]);
                mma_bf16(o[1][n16*2],   A1, Bv[0], Bv[1]);
                mma_bf16(o[1][n16*2+1], A1, Bv[2], Bv[3]);
            }
        }
    }

    // ---- row sums: quad shuffles then cross-colgroup smem atomics ----
    #pragma unroll
    for (int i = 0; i < 4; i++) {
        lr[i] += __shfl_xor_sync(0xffffffffu, lr[i], 1);
        lr[i] += __shfl_xor_sync(0xffffffffu, lr[i], 2);
    }
    if ((lane & 3) == 0) {
        const int r = rs + (lane >> 2);
        atomicAdd(&ls[r],      lr[0]);
        atomicAdd(&ls[r + 8],  lr[1]);
        atomicAdd(&ls[r + 16], lr[2]);
        atomicAdd(&ls[r + 24], lr[3]);
    }
    __syncthreads();

    // ---- epilogue: y = gamma * O/l + x ----
    const float gamma = *gamma_p;
    #pragma unroll
    for (int m = 0; m < 2; m++) {
        const int ra = rs + 16*m + (lane >> 2);
        const int rb2 = ra + 8;
        const float ga = gamma / ls[ra];
        const float gb = gamma / ls[rb2];
        #pragma unroll
        for (int n = 0; n < 8; n++) {
            const float* oo = o[m][n];
            const int d = dh + (n>>1)*16 + (n&1)*8 + (lane & 3)*2;
            const size_t ea = (rowb + ra)*CDIM + d;
            const size_t eb = (rowb + rb2)*CDIM + d;
            float2 xa = *(const float2*)(x + ea);
            float2 xb = *(const float2*)(x + eb);
            float2 ya, yb;
            ya.x = fmaf(ga, oo[0], xa.x);
            ya.y = fmaf(ga, oo[1], xa.y);
            yb.x = fmaf(gb, oo[2], xb.x);
            yb.y = fmaf(gb, oo[3], xb.y);
            *(float2*)(out + ea) = ya;
            *(float2*)(out + eb) = yb;
        }
    }
}

// ============================================================================
extern "C" void kernel_launch(void* const* d_in, const int* in_sizes, int n_in,
                              void* d_out, int out_size)
{
    const float* x     = (const float*)d_in[0];
    const float* Wf    = (const float*)d_in[1];
    const float* bf    = (const float*)d_in[2];
    const float* Wg    = (const float*)d_in[3];
    const float* bg    = (const float*)d_in[4];
    const float* Wh    = (const float*)d_in[5];
    const float* bh    = (const float*)d_in[6];
    const float* gamma = (const float*)d_in[7];
    float* out = (float*)d_out;
    (void)in_sizes; (void)n_in; (void)out_size;

    cudaFuncSetAttribute(attn_kernel,
                         cudaFuncAttributeMaxDynamicSharedMemorySize, ATTN_SMEM);
    cudaFuncSetAttribute(proj_kernel,
                         cudaFuncAttributeMaxDynamicSharedMemorySize, PJ_SMEM);

    wsplit_kernel<<<320, 256>>>(Wf, Wg, Wh);
    xsplit_kernel<<<TOTPIX*CDIM/8/256, 256>>>(x);
    proj_kernel<<<dim3(TOTPIX/128, 5), 256, PJ_SMEM>>>(bf, bg, bh);
    attn_kernel<<<dim3(NPIX/128, NB), 512, ATTN_SMEM>>>(x, gamma, out);
}